// round 2
// baseline (speedup 1.0000x reference)
#include <cuda_runtime.h>

// WinCorr: out[s=(i,j,k), d,h,w] = scale * sum_c fixed[c,d,h,w] * moving[c, d+i-1, h+j-1, w+k-1]
// shapes: fixed/moving (1,32,96,96,96) f32; out (1,27,96,96,96) f32; zero padding.

#define CC   32
#define DD   96
#define HH   96
#define WW   96
#define HWSZ (HH * WW)
#define DHW  (DD * HWSZ)

#define WT   32            // w tile (== blockDim.x)
#define HT   16            // h tile (8 thread h-pairs)
#define SM_D 3
#define SM_H (HT + 2)      // 18
#define SM_W (WT + 2)      // 34
#define SM_N (SM_D * SM_H * SM_W)   // 1836 floats

__global__ __launch_bounds__(256, 2)
void wincorr_kernel(const float* __restrict__ fx,
                    const float* __restrict__ mv,
                    float* __restrict__ out)
{
    __shared__ float sm[2][SM_N];   // double buffer: one barrier per channel

    const int tx  = threadIdx.x;          // 0..31 -> w within tile
    const int ty  = threadIdx.y;          // 0..7  -> h pair within tile
    const int tid = ty * 32 + tx;

    const int w0 = blockIdx.x * WT;
    const int h0 = blockIdx.y * HT;
    const int d  = blockIdx.z;

    const int h = h0 + 2 * ty;            // this thread owns outputs at (d,h,w) and (d,h+1,w)
    const int w = w0 + tx;

    float acc0[27], acc1[27];
    #pragma unroll
    for (int s = 0; s < 27; ++s) { acc0[s] = 0.f; acc1[s] = 0.f; }

    const float* fptr = fx + (size_t)d * HWSZ + (size_t)h * WW + w;

    for (int c = 0; c < CC; ++c) {
        float* buf = sm[c & 1];

        // ---- cooperative load of moving tile (3 x 18 x 34) with zero padding ----
        const float* mc = mv + (size_t)c * DHW;
        #pragma unroll 1
        for (int idx = tid; idx < SM_N; idx += 256) {
            int dz = idx / (SM_H * SM_W);
            int r  = idx - dz * (SM_H * SM_W);
            int lh = r / SM_W;
            int lw = r - lh * SM_W;
            int gd = d  + dz - 1;
            int gh = h0 + lh - 1;
            int gw = w0 + lw - 1;
            float v = 0.f;
            if ((unsigned)gd < DD && (unsigned)gh < HH && (unsigned)gw < WW)
                v = __ldg(mc + (size_t)gd * HWSZ + (size_t)gh * WW + gw);
            buf[idx] = v;
        }

        // fixed values for this thread's two outputs (coalesced, used once each)
        const float f0 = __ldg(fptr + (size_t)c * DHW);
        const float f1 = __ldg(fptr + (size_t)c * DHW + WW);

        __syncthreads();   // tile visible; also protects prev buffer from overwrite next iter

        // ---- accumulate: 36 conflict-free LDS, 54 FMA per channel ----
        #pragma unroll
        for (int dz = 0; dz < 3; ++dz) {
            #pragma unroll
            for (int yy = 0; yy < 4; ++yy) {   // rows h-1 .. h+2
                const float* row = &buf[(dz * SM_H + 2 * ty + yy) * SM_W + tx];
                #pragma unroll
                for (int dk = 0; dk < 3; ++dk) {
                    const float m = row[dk];
                    if (yy < 3) acc0[dz * 9 + yy * 3 + dk]        += f0 * m;
                    if (yy > 0) acc1[dz * 9 + (yy - 1) * 3 + dk]  += f1 * m;
                }
            }
        }
        // no second barrier: next iteration writes the other buffer
    }

    const float scale = 0.17677669529663687f;   // 32^-0.5
    float* op = out + (size_t)d * HWSZ + (size_t)h * WW + w;
    #pragma unroll
    for (int s = 0; s < 27; ++s) {
        op[(size_t)s * DHW]      = acc0[s] * scale;
        op[(size_t)s * DHW + WW] = acc1[s] * scale;
    }
}

extern "C" void kernel_launch(void* const* d_in, const int* in_sizes, int n_in,
                              void* d_out, int out_size)
{
    const float* fixed  = (const float*)d_in[0];
    const float* moving = (const float*)d_in[1];
    float* out = (float*)d_out;

    dim3 block(32, 8, 1);
    dim3 grid(WW / WT, HH / HT, DD);   // (3, 6, 96)
    wincorr_kernel<<<grid, block>>>(fixed, moving, out);
}

// round 3
// speedup vs baseline: 3.3322x; 3.3322x over previous
#include <cuda_runtime.h>

// WinCorr: out[s=(i,j,k), d,h,w] = scale * sum_c fixed[c,d,h,w] * moving[c, d+i-1, h+j-1, w+k-1]
// shapes: fixed/moving (1,32,96,96,96) f32; out (1,27,96,96,96) f32; zero padding.

#define CC   32
#define DD   96
#define HH   96
#define WW   96
#define HWSZ (HH * WW)
#define DHW  (DD * HWSZ)

#define WT   32            // w tile (== blockDim.x)
#define HT   16            // h tile (8 thread h-pairs)
#define SM_D 3
#define SM_H (HT + 2)      // 18
#define SM_W (WT + 2)      // 34
#define SM_N (SM_D * SM_H * SM_W)   // 1836 floats
#define SM_STRIDE 2048     // padded buffer stride (floats) -> cheap buffer toggle
#define NLD  8             // ceil(1836/256)

__global__ __launch_bounds__(256, 2)
void wincorr_kernel(const float* __restrict__ fx,
                    const float* __restrict__ mv,
                    float* __restrict__ out)
{
    __shared__ float sm[2 * SM_STRIDE];

    const int tx  = threadIdx.x;          // 0..31 -> w within tile
    const int ty  = threadIdx.y;          // 0..7  -> h pair within tile
    const int tid = ty * 32 + tx;

    const int w0 = blockIdx.x * WT;
    const int h0 = blockIdx.y * HT;
    const int d  = blockIdx.z;

    const int h = h0 + 2 * ty;            // outputs at (d,h,w) and (d,h+1,w)
    const int w = w0 + tx;

    // ---- one-time: per-thread load offsets + validity (c-invariant) ----
    int  off[NLD];
    bool gvalid[NLD];                     // global address in range (else slot must be 0)
    #pragma unroll
    for (int it = 0; it < NLD; ++it) {
        int idx = tid + it * 256;
        int dz  = idx / (SM_H * SM_W);
        int r   = idx - dz * (SM_H * SM_W);
        int lh  = r / SM_W;
        int lw  = r - lh * SM_W;
        int gd  = d  + dz - 1;
        int gh  = h0 + lh - 1;
        int gw  = w0 + lw - 1;
        gvalid[it] = (idx < SM_N) &&
                     ((unsigned)gd < DD) && ((unsigned)gh < HH) && ((unsigned)gw < WW);
        off[it] = gvalid[it] ? (gd * HWSZ + gh * WW + gw) : 0;
    }
    const bool svalid[NLD] = { true, true, true, true, true, true, true,
                               (tid < SM_N - 7 * 256) };   // last partial chunk

    float acc0[27], acc1[27];
    #pragma unroll
    for (int s = 0; s < 27; ++s) { acc0[s] = 0.f; acc1[s] = 0.f; }

    // ---- prefetch channel 0 into registers ----
    const float* mc = mv;
    const float* fp = fx + (size_t)d * HWSZ + (size_t)h * WW + w;
    float rg[NLD];
    #pragma unroll
    for (int it = 0; it < NLD; ++it)
        rg[it] = gvalid[it] ? __ldg(mc + off[it]) : 0.f;
    float fa = __ldg(fp);
    float fb = __ldg(fp + WW);

    for (int c = 0; c < CC; ++c) {
        float* buf = sm + (c & 1) * SM_STRIDE;

        // commit staged tile for channel c (pad slots get explicit 0)
        #pragma unroll
        for (int it = 0; it < NLD; ++it)
            if (svalid[it]) buf[tid + it * 256] = rg[it];

        const float f0 = fa, f1 = fb;
        __syncthreads();                  // tile c visible; prev buffer free

        // prefetch channel c+1 (long-latency loads overlap the FMA block below)
        if (c + 1 < CC) {
            mc += DHW;
            fp += DHW;
            #pragma unroll
            for (int it = 0; it < NLD; ++it)
                rg[it] = gvalid[it] ? __ldg(mc + off[it]) : 0.f;
            fa = __ldg(fp);
            fb = __ldg(fp + WW);
        }

        // ---- accumulate: 36 LDS (all [base+imm]) + 54 FFMA ----
        const float* base = buf + (2 * ty) * SM_W + tx;
        #pragma unroll
        for (int dz = 0; dz < 3; ++dz) {
            #pragma unroll
            for (int yy = 0; yy < 4; ++yy) {   // rows h-1 .. h+2
                #pragma unroll
                for (int dk = 0; dk < 3; ++dk) {
                    const float m = base[(dz * SM_H + yy) * SM_W + dk];
                    if (yy < 3) acc0[dz * 9 + yy * 3 + dk]       += f0 * m;
                    if (yy > 0) acc1[dz * 9 + (yy - 1) * 3 + dk] += f1 * m;
                }
            }
        }
        // no trailing barrier: next iteration writes the other buffer,
        // and the __syncthreads() above orders reads-before-overwrite.
    }

    const float scale = 0.17677669529663687f;   // 32^-0.5
    float* op = out + (size_t)d * HWSZ + (size_t)h * WW + w;
    #pragma unroll
    for (int s = 0; s < 27; ++s) {
        op[(size_t)s * DHW]      = acc0[s] * scale;
        op[(size_t)s * DHW + WW] = acc1[s] * scale;
    }
}

extern "C" void kernel_launch(void* const* d_in, const int* in_sizes, int n_in,
                              void* d_out, int out_size)
{
    const float* fixed  = (const float*)d_in[0];
    const float* moving = (const float*)d_in[1];
    float* out = (float*)d_out;

    dim3 block(32, 8, 1);
    dim3 grid(WW / WT, HH / HT, DD);   // (3, 6, 96)
    wincorr_kernel<<<grid, block>>>(fixed, moving, out);
}

// round 4
// speedup vs baseline: 3.3680x; 1.0107x over previous
#include <cuda_runtime.h>

// WinCorr: out[s=(i,j,k), d,h,w] = scale * sum_c fixed[c,d,h,w] * moving[c, d+i-1, h+j-1, w+k-1]
// fixed/moving (1,32,96,96,96) f32; out (1,27,96,96,96) f32; zero padding.

#define CC   32
#define DD   96
#define HH   96
#define WW   96
#define HWSZ (HH * WW)
#define DHW  (DD * HWSZ)

#define WT   32
#define HT   16
#define SM_D 3
#define SM_H (HT + 2)      // 18
#define SM_W (WT + 2)      // 34
#define SM_N (SM_D * SM_H * SM_W)   // 1836
#define SM_PAD 2048        // buffer stride (floats); slots [1836,2048) unused
#define NLD  8             // ceil(1836/256)

__device__ __forceinline__ void cp_async4(unsigned saddr, const void* gaddr) {
    asm volatile("cp.async.ca.shared.global [%0], [%1], 4;\n" :: "r"(saddr), "l"(gaddr));
}
__device__ __forceinline__ void cp_commit() {
    asm volatile("cp.async.commit_group;\n" ::: "memory");
}
__device__ __forceinline__ void cp_wait0() {
    asm volatile("cp.async.wait_group 0;\n" ::: "memory");
}

__global__ __launch_bounds__(256, 3)
void wincorr_kernel(const float* __restrict__ fx,
                    const float* __restrict__ mv,
                    float* __restrict__ out)
{
    __shared__ float sm[2][SM_PAD];

    const int tx  = threadIdx.x;
    const int ty  = threadIdx.y;
    const int tid = ty * 32 + tx;

    const int w0 = blockIdx.x * WT;
    const int h0 = blockIdx.y * HT;
    const int d  = blockIdx.z;

    const int h = h0 + 2 * ty;            // outputs (d,h,w) and (d,h+1,w)
    const int w = w0 + tx;

    // ---- per-thread c-invariant source byte-offsets; -1 = invalid (stays zero) ----
    long long off[NLD];
    #pragma unroll
    for (int it = 0; it < NLD; ++it) {
        int idx = tid + it * 256;
        int dz  = idx / (SM_H * SM_W);
        int r   = idx - dz * (SM_H * SM_W);
        int lh  = r / SM_W;
        int lw  = r - lh * SM_W;
        int gd  = d  + dz - 1;
        int gh  = h0 + lh - 1;
        int gw  = w0 + lw - 1;
        bool v = (idx < SM_N) &&
                 ((unsigned)gd < DD) && ((unsigned)gh < HH) && ((unsigned)gw < WW);
        off[it] = v ? (long long)(gd * HWSZ + gh * WW + gw) * 4 : -1;
    }

    // ---- pre-zero both buffers once (halo/pad slots keep these zeros forever) ----
    #pragma unroll
    for (int it = 0; it < NLD; ++it) {
        sm[0][tid + it * 256] = 0.f;
        sm[1][tid + it * 256] = 0.f;
    }
    __syncthreads();   // zeros drained before any cp.async lands

    const unsigned sbase0 = (unsigned)__cvta_generic_to_shared(&sm[0][tid]);
    const unsigned sbase1 = (unsigned)__cvta_generic_to_shared(&sm[1][tid]);
    const char* mcb = (const char*)mv;

    // ---- prologue: start channel 0 tile, prefetch fixed(0) ----
    #pragma unroll
    for (int it = 0; it < NLD; ++it)
        if (off[it] >= 0) cp_async4(sbase0 + it * 1024, mcb + off[it]);
    cp_commit();

    const float* fp = fx + (size_t)d * HWSZ + (size_t)h * WW + w;
    float fa = __ldg(fp);
    float fb = __ldg(fp + WW);

    float acc0[27], acc1[27];
    #pragma unroll
    for (int s = 0; s < 27; ++s) { acc0[s] = 0.f; acc1[s] = 0.f; }

    #pragma unroll 2
    for (int c = 0; c < CC; ++c) {
        cp_wait0();         // tile c resident (this thread's slots)
        __syncthreads();    // all slots visible; everyone done reading buf (c-1)

        // launch tile c+1 into the other buffer (overlaps compute below)
        if (c + 1 < CC) {
            mcb += DHW * 4;
            const unsigned sb = ((c + 1) & 1) ? sbase1 : sbase0;
            #pragma unroll
            for (int it = 0; it < NLD; ++it)
                if (off[it] >= 0) cp_async4(sb + it * 1024, mcb + off[it]);
            cp_commit();
        }

        const float f0 = fa, f1 = fb;
        if (c + 1 < CC) {
            fp += DHW;
            fa = __ldg(fp);
            fb = __ldg(fp + WW);
        }

        // ---- 36 LDS + 54 FFMA ----
        const float* base = &sm[c & 1][(2 * ty) * SM_W + tx];
        #pragma unroll
        for (int dz = 0; dz < 3; ++dz) {
            #pragma unroll
            for (int yy = 0; yy < 4; ++yy) {
                #pragma unroll
                for (int dk = 0; dk < 3; ++dk) {
                    const float m = base[(dz * SM_H + yy) * SM_W + dk];
                    if (yy < 3) acc0[dz * 9 + yy * 3 + dk]       += f0 * m;
                    if (yy > 0) acc1[dz * 9 + (yy - 1) * 3 + dk] += f1 * m;
                }
            }
        }
    }

    const float scale = 0.17677669529663687f;   // 32^-0.5
    float* op = out + (size_t)d * HWSZ + (size_t)h * WW + w;
    #pragma unroll
    for (int s = 0; s < 27; ++s) {
        op[(size_t)s * DHW]      = acc0[s] * scale;
        op[(size_t)s * DHW + WW] = acc1[s] * scale;
    }
}

extern "C" void kernel_launch(void* const* d_in, const int* in_sizes, int n_in,
                              void* d_out, int out_size)
{
    const float* fixed  = (const float*)d_in[0];
    const float* moving = (const float*)d_in[1];
    float* out = (float*)d_out;

    dim3 block(32, 8, 1);
    dim3 grid(WW / WT, HH / HT, DD);   // (3, 6, 96)
    wincorr_kernel<<<grid, block>>>(fixed, moving, out);
}

// round 5
// speedup vs baseline: 4.9731x; 1.4766x over previous
#include <cuda_runtime.h>

// WinCorr: out[s=(i,j,k), d,h,w] = scale * sum_c fixed[c,d,h,w] * moving[c, d+i-1, h+j-1, w+k-1]
// fixed/moving (1,32,96,96,96) f32; out (1,27,96,96,96) f32; zero padding.

#define CC   32
#define DD   96
#define HH   96
#define WW   96
#define HWSZ (HH * WW)
#define DHW  (DD * HWSZ)

#define WT   32
#define HT   16
#define SM_D 3
#define SM_H (HT + 2)          // 18
#define ROWS (SM_D * SM_H)     // 54 rows per tile
#define RW   40                // row width in words (160B, 16B-multiple)
#define TILE_W (ROWS * RW)     // 2160 words
#define TILE_B (TILE_W * 4)    // 8640 bytes
#define NSTAGE 4
#define QPR  10                // 16B chunks per row
#define TOTOPS (ROWS * QPR)    // 540 cp.async ops per tile
#define NOPS 3                 // ceil(540/256) per thread

__device__ __forceinline__ void cp_async16(unsigned saddr, const void* gaddr) {
    asm volatile("cp.async.cg.shared.global [%0], [%1], 16;\n" :: "r"(saddr), "l"(gaddr));
}
__device__ __forceinline__ void cp_commit() {
    asm volatile("cp.async.commit_group;\n" ::: "memory");
}
__device__ __forceinline__ void cp_wait2() {
    asm volatile("cp.async.wait_group 2;\n" ::: "memory");
}

__global__ __launch_bounds__(256, 3)
void wincorr_kernel(const float* __restrict__ fx,
                    const float* __restrict__ mv,
                    float* __restrict__ out)
{
    __shared__ float sm[NSTAGE * TILE_W];

    const int tx  = threadIdx.x;
    const int ty  = threadIdx.y;
    const int tid = ty * 32 + tx;

    const int w0 = blockIdx.x * WT;
    const int h0 = blockIdx.y * HT;
    const int d  = blockIdx.z;

    const int h = h0 + 2 * ty;            // outputs (d,h,w) and (d,h+1,w)
    const int w = w0 + tx;

    // ---- pre-zero all stage buffers; OOB slots stay zero for the whole kernel ----
    #pragma unroll
    for (int i = tid; i < NSTAGE * TILE_W; i += 256) sm[i] = 0.f;

    // ---- per-thread c-invariant cp.async ops: src word-offset, dst byte-offset ----
    // global row source spans gw in [w0-4, w0+36): every 16B chunk aligned both sides.
    int      srcw[NOPS];
    unsigned dstb[NOPS];
    bool     val [NOPS];
    #pragma unroll
    for (int t = 0; t < NOPS; ++t) {
        int o = tid + t * 256;
        bool v = (o < TOTOPS);
        int r  = o / QPR;                 // row 0..53
        int q  = o - r * QPR;             // chunk 0..9
        int dz = r / SM_H;
        int lh = r - dz * SM_H;
        int gd = d  + dz - 1;
        int gh = h0 + lh - 1;
        int gs = w0 - 4 + 4 * q;          // chunk start gw
        v = v && ((unsigned)gd < DD) && ((unsigned)gh < HH) && (gs >= 0) && (gs + 4 <= WW);
        val[t]  = v;
        srcw[t] = v ? (gd * HWSZ + gh * WW + gs) : 0;
        dstb[t] = (unsigned)(r * (RW * 4) + q * 16);
    }

    __syncthreads();   // zeros visible before any cp.async lands

    const unsigned smb = (unsigned)__cvta_generic_to_shared(sm);
    const char* mvb = (const char*)mv;

    // ---- prologue: launch channels 0..2 ----
    #pragma unroll
    for (int c = 0; c < 3; ++c) {
        const unsigned sb = smb + (unsigned)(c & (NSTAGE - 1)) * TILE_B;
        #pragma unroll
        for (int t = 0; t < NOPS; ++t)
            if (val[t]) cp_async16(sb + dstb[t], mvb + ((size_t)c * DHW + srcw[t]) * 4);
        cp_commit();
    }

    const float* fp = fx + (size_t)d * HWSZ + (size_t)h * WW + w;
    float fa = __ldg(fp);
    float fb = __ldg(fp + WW);

    float acc0[27], acc1[27];
    #pragma unroll
    for (int s = 0; s < 27; ++s) { acc0[s] = 0.f; acc1[s] = 0.f; }

    #pragma unroll 4
    for (int c = 0; c < CC; ++c) {
        cp_wait2();         // group c complete (c+1, c+2 may still fly)
        __syncthreads();    // tile c visible to all; everyone done with buf (c-1)

        // launch channel c+3 into buf (c-1)&3 (empty commit past the end keeps
        // the group count uniform so wait_group 2 is always exactly "group c done")
        if (c + 3 < CC) {
            const unsigned sb = smb + (unsigned)((c + 3) & (NSTAGE - 1)) * TILE_B;
            #pragma unroll
            for (int t = 0; t < NOPS; ++t)
                if (val[t]) cp_async16(sb + dstb[t], mvb + ((size_t)(c + 3) * DHW + srcw[t]) * 4);
        }
        cp_commit();

        const float f0 = fa, f1 = fb;
        if (c + 1 < CC) {
            fp += DHW;
            fa = __ldg(fp);
            fb = __ldg(fp + WW);
        }

        // ---- 36 conflict-free LDS [R+imm] + 54 FFMA ----
        const float* base = sm + (c & (NSTAGE - 1)) * TILE_W + (2 * ty) * RW + 3 + tx;
        #pragma unroll
        for (int dz = 0; dz < 3; ++dz) {
            #pragma unroll
            for (int yy = 0; yy < 4; ++yy) {       // rows h-1 .. h+2
                #pragma unroll
                for (int kk = 0; kk < 3; ++kk) {
                    const float m = base[(dz * SM_H + yy) * RW + kk];
                    if (yy < 3) acc0[dz * 9 + yy * 3 + kk]       += f0 * m;
                    if (yy > 0) acc1[dz * 9 + (yy - 1) * 3 + kk] += f1 * m;
                }
            }
        }
    }

    const float scale = 0.17677669529663687f;   // 32^-0.5
    float* op = out + (size_t)d * HWSZ + (size_t)h * WW + w;
    #pragma unroll
    for (int s = 0; s < 27; ++s) {
        op[(size_t)s * DHW]      = acc0[s] * scale;
        op[(size_t)s * DHW + WW] = acc1[s] * scale;
    }
}

extern "C" void kernel_launch(void* const* d_in, const int* in_sizes, int n_in,
                              void* d_out, int out_size)
{
    const float* fixed  = (const float*)d_in[0];
    const float* moving = (const float*)d_in[1];
    float* out = (float*)d_out;

    dim3 block(32, 8, 1);
    dim3 grid(WW / WT, HH / HT, DD);   // (3, 6, 96)
    wincorr_kernel<<<grid, block>>>(fixed, moving, out);
}